// round 9
// baseline (speedup 1.0000x reference)
#include <cuda_runtime.h>

typedef unsigned long long u64;

static constexpr int Bb = 16;
static constexpr int CE = 1024;
static constexpr int Tt = 2048;
static constexpr int CC = 64;
static constexpr int Kk = 4096;

static constexpr long long O_CODES = 0;
static constexpr long long O_QUANT = 32768;
static constexpr long long N_QUANT = (long long)Bb * CE * Tt;    // 33554432
static constexpr long long O_CBL   = O_QUANT + N_QUANT;           // 33587200
static constexpr long long O_CML   = O_CBL + 1;
static constexpr long long O_XPROJ = O_CML + 1;                   // 33587202 (even -> 8B aligned)
static constexpr long long N_XP    = (long long)Bb * CC * Tt;     // 2097152
static constexpr long long O_QPROJ = O_XPROJ + N_XP;              // 35684354 (even)

// scratch (static device globals; no runtime allocation)
__device__ __align__(16) float  g_WdI[CE * 128];         // W_in dup, k-major: [k][o*2]  (o: 64)
__device__ __align__(16) float  g_WdO2[CC * 2048];       // W_out dup, k-major: [k][o*2] (o: 1024)
__device__ __align__(16) float  g_cbT[CC * Kk];          // (-2 * normalized codebook) [o][k]
__device__ __align__(16) float  g_cbn2[Kk];              // ||cb_n||^2
__device__ double g_lpart[512];

__device__ __forceinline__ u64 pk2(float lo, float hi) {
    u64 r; asm("mov.b64 %0, {%1, %2};" : "=l"(r) : "f"(lo), "f"(hi)); return r;
}
__device__ __forceinline__ float2 upk2(u64 v) {
    float2 r; asm("mov.b64 {%0, %1}, %2;" : "=f"(r.x), "=f"(r.y) : "l"(v)); return r;
}
__device__ __forceinline__ void fma2(u64 &d, u64 a, u64 b) {
    asm("fma.rn.f32x2 %0, %1, %2, %0;" : "+l"(d) : "l"(a), "l"(b));
}
__device__ __forceinline__ unsigned s2u(const void* p) {
    return (unsigned)__cvta_generic_to_shared(p);
}
__device__ __forceinline__ void cp16(unsigned s, const void* g) {
    asm volatile("cp.async.cg.shared.global [%0], [%1], 16;" :: "r"(s), "l"(g));
}
__device__ __forceinline__ void cp8(unsigned s, const void* g) {
    asm volatile("cp.async.ca.shared.global [%0], [%1], 8;" :: "r"(s), "l"(g));
}
__device__ __forceinline__ void cpcommit() { asm volatile("cp.async.commit_group;"); }
__device__ __forceinline__ void cpwait1()  { asm volatile("cp.async.wait_group 1;"); }

// ---------------- prep: weight-norm W_in -> dup k-major g_WdI ----------------
__global__ __launch_bounds__(256) void k_prep_win(const float* __restrict__ v_in,
                                                  const float* __restrict__ g_in)
{
    __shared__ float sb[256];
    __shared__ float snorm;
    int o = blockIdx.x, tid = threadIdx.x;
    float s = 0.f;
#pragma unroll
    for (int j = 0; j < 4; j++) { float v = v_in[o * CE + tid + j * 256]; s += v * v; }
    sb[tid] = s; __syncthreads();
    for (int off = 128; off > 0; off >>= 1) { if (tid < off) sb[tid] += sb[tid + off]; __syncthreads(); }
    if (tid == 0) snorm = __fsqrt_rn(sb[0]);
    __syncthreads();
    float n = snorm, g = g_in[o];
#pragma unroll
    for (int j = 0; j < 4; j++) {
        int i = tid + j * 256;
        float w = __fdiv_rn(g * v_in[o * CE + i], n);
        *(u64*)&g_WdI[i * 128 + o * 2] = pk2(w, w);
    }
}

// ---------------- prep: weight-norm W_out -> dup k-major g_WdO2 ----------------
__global__ __launch_bounds__(256) void k_prep_wout(const float* __restrict__ v_out,
                                                   const float* __restrict__ g_out)
{
    int gw = (blockIdx.x * 256 + threadIdx.x) >> 5;   // o_global 0..1023
    int l = threadIdx.x & 31;
    float a = v_out[gw * CC + l], b = v_out[gw * CC + l + 32];
    float s = a * a + b * b;
#pragma unroll
    for (int off = 16; off; off >>= 1) s += __shfl_xor_sync(0xffffffffu, s, off);
    float n = __fsqrt_rn(s), g = g_out[gw];
    float wa = __fdiv_rn(g * a, n);
    float wb = __fdiv_rn(g * b, n);
    *(u64*)&g_WdO2[l        * 2048 + gw * 2] = pk2(wa, wa);
    *(u64*)&g_WdO2[(l + 32) * 2048 + gw * 2] = pk2(wb, wb);
}

// ---------------- prep: normalize codebook -> (-2x) transposed + ||.||^2 ----------------
__global__ __launch_bounds__(256) void k_prep_cb(const float* __restrict__ cb)
{
    int k = (blockIdx.x * 256 + threadIdx.x) >> 5;
    int l = threadIdx.x & 31;
    float a = cb[k * CC + l], b = cb[k * CC + l + 32];
    float s = a * a + b * b;
#pragma unroll
    for (int off = 16; off; off >>= 1) s += __shfl_xor_sync(0xffffffffu, s, off);
    float n = fmaxf(__fsqrt_rn(s), 1e-12f);
    float ca = __fdiv_rn(a, n), cbv = __fdiv_rn(b, n);
    g_cbT[l * Kk + k]        = -2.f * ca;
    g_cbT[(l + 32) * Kk + k] = -2.f * cbv;
    float s2 = ca * ca + cbv * cbv;
#pragma unroll
    for (int off = 16; off; off >>= 1) s2 += __shfl_xor_sync(0xffffffffu, s2, off);
    if (l == 0) g_cbn2[k] = s2;
}

// ---------------- Out[32o x 128t] = W[32o x K] @ X[K x 128t], 2-stage cp.async ----------------
// 256 threads, thread = 4 o x 4 t; warp <-> one 4-o group so the dup-W read is a
// warp-broadcast (2 LDS.128); X is one lane-consecutive LDS.128 per k.
// Grid z picks the 32-o slice (col offset z*64 in the dup row).
static constexpr int XTS = 132;                 // X stage row stride (128t + pad)
static constexpr int WTS = 68;                  // W stage row stride (64 dup + pad)
static constexpr int XSTG = 32 * XTS;
static constexpr int WSTG = 32 * WTS;
static constexpr int SMEM_GEMM = (2 * XSTG + 2 * WSTG) * 4;   // 51200 B

template<bool XALN16>
__global__ __launch_bounds__(256) void k_gemm(const float* __restrict__ Wd, int Wrow, int K,
                                              const float* __restrict__ X, long long XyS,
                                              float* __restrict__ O, long long OyS)
{
    extern __shared__ float sm[];
    float* XsB = sm;                 // [2][XSTG]
    float* WsB = sm + 2 * XSTG;      // [2][WSTG]
    int tid = threadIdx.x;
    int to = tid >> 5;               // 0..7 : o-group of 4 (constant per warp)
    int t4 = tid & 31;               // t-slot of 4
    int wcol = blockIdx.z * 64;      // dup-col offset for this 32-o slice
    const float* Xp = X + (long long)blockIdx.y * XyS + (long long)blockIdx.x * 128;
    float* Op = O + (long long)blockIdx.y * OyS + (long long)blockIdx.z * 32 * Tt
                  + (long long)blockIdx.x * 128;

    auto load = [&](int st, int kc) {
        float* Ws = WsB + st * WSTG;
        float* Xs = XsB + st * XSTG;
#pragma unroll
        for (int it = 0; it < 2; it++) {
            int rr = tid + it * 256;             // 512 quads: 32 k x 16 q
            int k = rr >> 4, q = rr & 15;
            cp16(s2u(&Ws[k * WTS + q * 4]), &Wd[(long long)(kc + k) * Wrow + wcol + q * 4]);
        }
        if (XALN16) {
#pragma unroll
            for (int it = 0; it < 4; it++) {
                int rr = tid + it * 256;         // 1024 quads: 32 k x 32 q
                int k = rr >> 5, q = rr & 31;
                cp16(s2u(&Xs[k * XTS + q * 4]), &Xp[(long long)(kc + k) * Tt + q * 4]);
            }
        } else {
#pragma unroll
            for (int it = 0; it < 8; it++) {
                int rr = tid + it * 256;         // 2048 u64: 32 k x 64 q
                int k = rr >> 6, q = rr & 63;
                cp8(s2u(&Xs[k * XTS + q * 2]), &Xp[(long long)(kc + k) * Tt + q * 2]);
            }
        }
    };

    u64 acc[4][2];
#pragma unroll
    for (int i = 0; i < 4; i++) { acc[i][0] = 0ull; acc[i][1] = 0ull; }

    load(0, 0); cpcommit();
    int nch = K >> 5;
    for (int c = 0; c < nch; c++) {
        if (c + 1 < nch) load((c + 1) & 1, (c + 1) << 5);
        cpcommit();
        cpwait1();
        __syncthreads();
        const float* Xs = XsB + (c & 1) * XSTG;
        const float* Ws = WsB + (c & 1) * WSTG;
#pragma unroll 8
        for (int k = 0; k < 32; k++) {
            const u64* xp = (const u64*)&Xs[k * XTS + t4 * 4];
            u64 xa = xp[0], xb = xp[1];
            const u64* wp = (const u64*)&Ws[k * WTS + to * 8];   // broadcast
            u64 w0 = wp[0], w1 = wp[1], w2 = wp[2], w3 = wp[3];
            fma2(acc[0][0], w0, xa); fma2(acc[0][1], w0, xb);
            fma2(acc[1][0], w1, xa); fma2(acc[1][1], w1, xb);
            fma2(acc[2][0], w2, xa); fma2(acc[2][1], w2, xb);
            fma2(acc[3][0], w3, xa); fma2(acc[3][1], w3, xb);
        }
        __syncthreads();
    }
#pragma unroll
    for (int oj = 0; oj < 4; oj++) {
        long long rb = (long long)(to * 4 + oj) * Tt + t4 * 4;
        *(u64*)&Op[rb]     = acc[oj][0];
        *(u64*)&Op[rb + 2] = acc[oj][1];
    }
}

// ---------------- dist + argmin + gather + qproj + loss partials ----------------
// block = 64 t, 256 threads; 64 chunks of 64 k, 2-stage cp.async on the codebook.
// thread = 4 t x 4 k; dup-E 2-way-broadcast read, C lane-consecutive LDS.128.
// cbT pre-scaled by -2; acc initialized from ||cb_n||^2 -> accumulator IS the score.
static constexpr int ETS = 132;                  // Es2 row stride (64t dup + pad)
static constexpr int CTS = 68;                   // Cs row stride (64k + pad)
static constexpr int CSTG = 64 * CTS;
static constexpr int SMEM_DIST = (64 * ETS + 2 * CSTG + 2 * 64 + 64 + 64) * 4;   // 69632 B

__global__ __launch_bounds__(256) void k_dist(const float* __restrict__ cb,
                                              float* __restrict__ out)
{
    extern __shared__ float sm[];
    float* Es2   = sm;                           // [64 o][132] dup t
    float* CsB   = sm + 64 * ETS;                // [2][64 o][68]
    float* cb2   = sm + 64 * ETS + 2 * CSTG;     // [2][64]
    float* den   = cb2 + 128;                    // [64]
    int*   scode = (int*)(den + 64);             // [64]
    float* redv  = CsB;                          // overlap after chunk loop
    int*   redi  = (int*)(CsB + 1024);

    int b = blockIdx.y, tid = threadIdx.x;
    long long t0 = (long long)blockIdx.x * 64;
    int tx = tid & 15;           // k-slot of 4
    int ty = tid >> 4;           // 0..15 : t-group of 4 (2 groups per warp)
    const long long xbase = O_XPROJ + (long long)b * (CC * Tt) + t0;

    // stage plain x_proj tile into Cs stage 0 (free until chunk loop)
#pragma unroll
    for (int it = 0; it < 8; it++) {
        int rr = tid + it * 256;                 // 2048 u64: 64 o x 32 t2
        int o = rr >> 5, t2 = rr & 31;
        *(u64*)&CsB[o * CTS + t2 * 2] = *(const u64*)&out[xbase + (long long)o * Tt + t2 * 2];
    }
    __syncthreads();
    if (tid < 64) {
        float s = 0.f;
#pragma unroll 8
        for (int o = 0; o < 64; o++) { float v = CsB[o * CTS + tid]; s += v * v; }
        den[tid] = fmaxf(__fsqrt_rn(s), 1e-12f);
    }
    __syncthreads();
#pragma unroll
    for (int it = 0; it < 8; it++) {
        int rr = tid + it * 256;
        int o = rr >> 5, t2 = rr & 31;
        float2 v = upk2(*(const u64*)&CsB[o * CTS + t2 * 2]);
        float e0 = __fdiv_rn(v.x, den[t2 * 2]);
        float e1 = __fdiv_rn(v.y, den[t2 * 2 + 1]);
        *(u64*)&Es2[o * ETS + t2 * 4]     = pk2(e0, e0);
        *(u64*)&Es2[o * ETS + t2 * 4 + 2] = pk2(e1, e1);
    }
    __syncthreads();                             // Cs0 reads done before prefetch overwrites

    auto loadc = [&](int st, int kc0) {
        float* Cs = CsB + st * CSTG;
#pragma unroll
        for (int it = 0; it < 4; it++) {
            int rr = tid + it * 256;             // 1024 quads: 64 o x 16 k4
            int o = rr >> 4, k4 = rr & 15;
            cp16(s2u(&Cs[o * CTS + k4 * 4]), &g_cbT[o * Kk + kc0 + k4 * 4]);
        }
        if (tid < 16) cp16(s2u(&cb2[st * 64 + tid * 4]), &g_cbn2[kc0 + tid * 4]);
    };

    float bval[4]; int bidx[4];
#pragma unroll
    for (int i = 0; i < 4; i++) { bval[i] = 3.4028235e38f; bidx[i] = 0; }

    loadc(0, 0); cpcommit();
    for (int ch = 0; ch < 64; ch++) {
        if (ch + 1 < 64) loadc((ch + 1) & 1, (ch + 1) * 64);
        cpcommit();
        cpwait1();
        __syncthreads();
        const float* Cs = CsB + (ch & 1) * CSTG;
        const float* cbn2s = cb2 + (ch & 1) * 64;
        int kc0 = ch * 64;

        const u64* ip = (const u64*)&cbn2s[tx * 4];
        u64 i0 = ip[0], i1 = ip[1];
        u64 acc[4][2];
#pragma unroll
        for (int tl = 0; tl < 4; tl++) { acc[tl][0] = i0; acc[tl][1] = i1; }

#pragma unroll 8
        for (int o = 0; o < 64; o++) {
            const u64* cp = (const u64*)&Cs[o * CTS + tx * 4];
            u64 c0 = cp[0], c1 = cp[1];
            const u64* ep = (const u64*)&Es2[o * ETS + ty * 8];   // 2-way broadcast
            u64 e0 = ep[0], e1 = ep[1], e2 = ep[2], e3 = ep[3];
            fma2(acc[0][0], e0, c0); fma2(acc[0][1], e0, c1);
            fma2(acc[1][0], e1, c0); fma2(acc[1][1], e1, c1);
            fma2(acc[2][0], e2, c0); fma2(acc[2][1], e2, c1);
            fma2(acc[3][0], e3, c0); fma2(acc[3][1], e3, c1);
        }
#pragma unroll
        for (int tl = 0; tl < 4; tl++) {
#pragma unroll
            for (int j = 0; j < 2; j++) {
                float2 d = upk2(acc[tl][j]);
                int kg = kc0 + tx * 4 + j * 2;
                if (d.x < bval[tl]) { bval[tl] = d.x; bidx[tl] = kg; }
                if (d.y < bval[tl]) { bval[tl] = d.y; bidx[tl] = kg + 1; }
            }
        }
        __syncthreads();
    }
#pragma unroll
    for (int tl = 0; tl < 4; tl++) {
        redv[(ty * 4 + tl) * 16 + tx] = bval[tl];
        redi[(ty * 4 + tl) * 16 + tx] = bidx[tl];
    }
    __syncthreads();
    if (tid < 64) {
        float bv = 3.4028235e38f; int bi = 0x7fffffff;
#pragma unroll
        for (int j = 0; j < 16; j++) {
            float v = redv[tid * 16 + j]; int i = redi[tid * 16 + j];
            if (v < bv || (v == bv && i < bi)) { bv = v; bi = i; }
        }
        scode[tid] = bi;
        out[O_CODES + (long long)b * Tt + t0 + tid] = (float)bi;
    }
    __syncthreads();

    // gather q, write quantized_proj = xp + (q - xp), accumulate loss
    {
        int t = tid & 63, og = tid >> 6;         // og 0..3 -> 16 o each
        int code = scode[t];
        const float* cbrow = cb + (long long)code * CC + og * 16;
        long long xb2 = O_XPROJ + (long long)b * (CC * Tt) + t0 + t;
        long long qb2 = O_QPROJ + (long long)b * (CC * Tt) + t0 + t;
        float ls = 0.f;
#pragma unroll
        for (int j = 0; j < 16; j++) {
            long long ro = (long long)(og * 16 + j) * Tt;
            float xp = out[xb2 + ro];
            float q  = cbrow[j];
            float d  = q - xp;
            out[qb2 + ro] = xp + d;
            ls += d * d;
        }
        __syncthreads();
        redv[tid] = ls; __syncthreads();
        for (int off = 128; off > 0; off >>= 1) {
            if (tid < off) redv[tid] += redv[tid + off];
            __syncthreads();
        }
        if (tid == 0) g_lpart[blockIdx.y * gridDim.x + blockIdx.x] = (double)redv[0];
    }
}

// ---------------- final loss reduction ----------------
__global__ __launch_bounds__(512) void k_loss(float* __restrict__ out)
{
    __shared__ double sb[512];
    int tid = threadIdx.x;
    sb[tid] = g_lpart[tid];
    __syncthreads();
    for (int off = 256; off > 0; off >>= 1) {
        if (tid < off) sb[tid] += sb[tid + off];
        __syncthreads();
    }
    if (tid == 0) {
        float l = (float)(sb[0] / (double)(16.0 * 64.0 * 2048.0));
        out[O_CBL] = l;
        out[O_CML] = l;
    }
}

extern "C" void kernel_launch(void* const* d_in, const int* in_sizes, int n_in,
                              void* d_out, int out_size) {
    (void)in_sizes; (void)n_in; (void)out_size;
    const float* x    = (const float*)d_in[0];
    const float* v_in = (const float*)d_in[1];
    const float* g_in = (const float*)d_in[2];
    const float* v_out= (const float*)d_in[3];
    const float* g_out= (const float*)d_in[4];
    const float* cb   = (const float*)d_in[5];
    float* out = (float*)d_out;

    cudaFuncSetAttribute(k_gemm<true>,  cudaFuncAttributeMaxDynamicSharedMemorySize, SMEM_GEMM);
    cudaFuncSetAttribute(k_gemm<false>, cudaFuncAttributeMaxDynamicSharedMemorySize, SMEM_GEMM);
    cudaFuncSetAttribute(k_dist, cudaFuncAttributeMaxDynamicSharedMemorySize, SMEM_DIST);

    k_prep_win<<<64, 256>>>(v_in, g_in);
    k_prep_wout<<<128, 256>>>(v_out, g_out);
    k_prep_cb<<<512, 256>>>(cb);

    float* wdi; cudaGetSymbolAddress((void**)&wdi, g_WdI);
    float* wdo; cudaGetSymbolAddress((void**)&wdo, g_WdO2);

    // x_proj = W_in @ x : 16 t-tiles x 16 b x 2 o-slices = 512 blocks
    k_gemm<true><<<dim3(16, 16, 2), 256, SMEM_GEMM>>>(wdi, 128, CE,
                                                      x, (long long)CE * Tt,
                                                      out + O_XPROJ, (long long)CC * Tt);

    // codes / qproj / loss partials : 32 t-tiles x 16 b = 512 blocks
    k_dist<<<dim3(32, 16), 256, SMEM_DIST>>>(cb, out);
    k_loss<<<1, 512>>>(out);

    // quantized = W_out @ quantized_proj : 16 t x 16 b x 32 o-slices = 8192 blocks
    k_gemm<false><<<dim3(16, 16, 32), 256, SMEM_GEMM>>>(wdo, 2048, CC,
                                                        out + O_QPROJ, (long long)CC * Tt,
                                                        out + O_QUANT, (long long)CE * Tt);
}

// round 10
// speedup vs baseline: 1.3787x; 1.3787x over previous
#include <cuda_runtime.h>

typedef unsigned long long u64;

static constexpr int Bb = 16;
static constexpr int CE = 1024;
static constexpr int Tt = 2048;
static constexpr int CC = 64;
static constexpr int Kk = 4096;

static constexpr long long O_CODES = 0;
static constexpr long long O_QUANT = 32768;
static constexpr long long N_QUANT = (long long)Bb * CE * Tt;    // 33554432
static constexpr long long O_CBL   = O_QUANT + N_QUANT;           // 33587200
static constexpr long long O_CML   = O_CBL + 1;
static constexpr long long O_XPROJ = O_CML + 1;                   // 33587202 (even -> 8B aligned)
static constexpr long long N_XP    = (long long)Bb * CC * Tt;     // 2097152
static constexpr long long O_QPROJ = O_XPROJ + N_XP;              // 35684354 (even)

// scratch (static device globals; no runtime allocation)
__device__ __align__(16) float  g_Win[CC * CE];
__device__ __align__(16) float  g_Wout[CE * CC];
__device__ __align__(16) float  g_cbT[CC * Kk];    // (-2 * normalized codebook), [o][k]
__device__ __align__(16) float  g_cbn2[Kk];        // ||cb_n||^2
__device__ double g_lpart[256];

__device__ __forceinline__ u64 pk2(float lo, float hi) {
    u64 r; asm("mov.b64 %0, {%1, %2};" : "=l"(r) : "f"(lo), "f"(hi)); return r;
}
__device__ __forceinline__ float2 upk2(u64 v) {
    float2 r; asm("mov.b64 {%0, %1}, %2;" : "=f"(r.x), "=f"(r.y) : "l"(v)); return r;
}
__device__ __forceinline__ void fma2(u64 &d, u64 a, u64 b) {
    asm("fma.rn.f32x2 %0, %1, %2, %0;" : "+l"(d) : "l"(a), "l"(b));
}
__device__ __forceinline__ unsigned s2u(const void* p) {
    return (unsigned)__cvta_generic_to_shared(p);
}
__device__ __forceinline__ void cp16(unsigned s, const void* g) {
    asm volatile("cp.async.cg.shared.global [%0], [%1], 16;" :: "r"(s), "l"(g));
}
__device__ __forceinline__ void cpcommit() { asm volatile("cp.async.commit_group;"); }
__device__ __forceinline__ void cpwait1()  { asm volatile("cp.async.wait_group 1;"); }

// ---------------- prep: weight-norm W_in (rows of 1024) ----------------
__global__ __launch_bounds__(256) void k_prep_win(const float* __restrict__ v_in,
                                                  const float* __restrict__ g_in)
{
    __shared__ float sb[256];
    __shared__ float snorm;
    int o = blockIdx.x, tid = threadIdx.x;
    float s = 0.f;
#pragma unroll
    for (int j = 0; j < 4; j++) { float v = v_in[o * CE + tid + j * 256]; s += v * v; }
    sb[tid] = s; __syncthreads();
    for (int off = 128; off > 0; off >>= 1) { if (tid < off) sb[tid] += sb[tid + off]; __syncthreads(); }
    if (tid == 0) snorm = __fsqrt_rn(sb[0]);
    __syncthreads();
    float n = snorm, g = g_in[o];
#pragma unroll
    for (int j = 0; j < 4; j++) {
        int i = tid + j * 256;
        g_Win[o * CE + i] = __fdiv_rn(g * v_in[o * CE + i], n);
    }
}

// ---------------- prep: weight-norm W_out (rows of 64), warp/row ----------------
__global__ __launch_bounds__(256) void k_prep_wout(const float* __restrict__ v_out,
                                                   const float* __restrict__ g_out)
{
    int gw = (blockIdx.x * 256 + threadIdx.x) >> 5;
    int l = threadIdx.x & 31;
    float a = v_out[gw * CC + l], b = v_out[gw * CC + l + 32];
    float s = a * a + b * b;
#pragma unroll
    for (int off = 16; off; off >>= 1) s += __shfl_xor_sync(0xffffffffu, s, off);
    float n = __fsqrt_rn(s), g = g_out[gw];
    g_Wout[gw * CC + l]      = __fdiv_rn(g * a, n);
    g_Wout[gw * CC + l + 32] = __fdiv_rn(g * b, n);
}

// ---------------- prep: normalize codebook -> (-2x) transposed + ||.||^2 ----------------
__global__ __launch_bounds__(256) void k_prep_cb(const float* __restrict__ cb)
{
    int k = (blockIdx.x * 256 + threadIdx.x) >> 5;
    int l = threadIdx.x & 31;
    float a = cb[k * CC + l], b = cb[k * CC + l + 32];
    float s = a * a + b * b;
#pragma unroll
    for (int off = 16; off; off >>= 1) s += __shfl_xor_sync(0xffffffffu, s, off);
    float n = fmaxf(__fsqrt_rn(s), 1e-12f);
    float ca = __fdiv_rn(a, n), cbv = __fdiv_rn(b, n);
    g_cbT[l * Kk + k]        = -2.f * ca;
    g_cbT[(l + 32) * Kk + k] = -2.f * cbv;
    float s2 = ca * ca + cbv * cbv;
#pragma unroll
    for (int off = 16; off; off >>= 1) s2 += __shfl_xor_sync(0xffffffffu, s2, off);
    if (l == 0) g_cbn2[k] = s2;
}

// ---------------- R3 gemm (proven): Out[64 x 128t] = W[64 x K] @ X[K x 128t] ----------------
// block = 64 o x 128 t; thread tile 4o x 8t (two strided float4 t-groups)
template<bool XALN16>
__global__ __launch_bounds__(256) void k_gemm64(const float* __restrict__ W, int K, long long WzS,
                                                const float* __restrict__ X, long long XyS,
                                                float* __restrict__ O, long long OyS, long long OzS)
{
    __shared__ __align__(16) float Ws[32][68];
    __shared__ __align__(16) float Xs[32][128];
    const float* Wp = W + (long long)blockIdx.z * WzS;
    const float* Xp = X + (long long)blockIdx.y * XyS;
    float* Op = O + (long long)blockIdx.y * OyS + (long long)blockIdx.z * OzS + (long long)blockIdx.x * 128;
    int tid = threadIdx.x;
    int to = tid >> 4, tt = tid & 15;
    long long t0 = (long long)blockIdx.x * 128;

    u64 acc[4][4];
#pragma unroll
    for (int i = 0; i < 4; i++)
#pragma unroll
        for (int j = 0; j < 4; j++) acc[i][j] = 0ull;

    for (int kc = 0; kc < K; kc += 32) {
#pragma unroll
        for (int it = 0; it < 2; it++) {
            int rr = tid + it * 256;                 // 512 quads: 64 o x 8 kq
            int o = rr >> 3, kq = rr & 7;
            float4 w = *(const float4*)&Wp[(long long)o * K + kc + kq * 4];
            Ws[kq * 4 + 0][o] = w.x; Ws[kq * 4 + 1][o] = w.y;
            Ws[kq * 4 + 2][o] = w.z; Ws[kq * 4 + 3][o] = w.w;
        }
#pragma unroll
        for (int it = 0; it < 4; it++) {
            int rr = tid + it * 256;                 // 1024 quads: 32 k x 32 t4
            int i = rr >> 5, t4 = rr & 31;
            long long gidx = (long long)(kc + i) * Tt + t0 + t4 * 4;
            if (XALN16) {
                *(float4*)&Xs[i][t4 * 4] = *(const float4*)&Xp[gidx];
            } else {
                const u64* p = (const u64*)&Xp[gidx];
                *(u64*)&Xs[i][t4 * 4]     = p[0];
                *(u64*)&Xs[i][t4 * 4 + 2] = p[1];
            }
        }
        __syncthreads();
#pragma unroll 8
        for (int k = 0; k < 32; k++) {
            float4 w  = *(const float4*)&Ws[k][to * 4];
            float4 xa = *(const float4*)&Xs[k][tt * 4];
            float4 xb = *(const float4*)&Xs[k][64 + tt * 4];
            u64 xa0 = pk2(xa.x, xa.y), xa1 = pk2(xa.z, xa.w);
            u64 xb0 = pk2(xb.x, xb.y), xb1 = pk2(xb.z, xb.w);
            u64 w0 = pk2(w.x, w.x), w1 = pk2(w.y, w.y), w2 = pk2(w.z, w.z), w3 = pk2(w.w, w.w);
            fma2(acc[0][0], w0, xa0); fma2(acc[0][1], w0, xa1); fma2(acc[0][2], w0, xb0); fma2(acc[0][3], w0, xb1);
            fma2(acc[1][0], w1, xa0); fma2(acc[1][1], w1, xa1); fma2(acc[1][2], w1, xb0); fma2(acc[1][3], w1, xb1);
            fma2(acc[2][0], w2, xa0); fma2(acc[2][1], w2, xa1); fma2(acc[2][2], w2, xb0); fma2(acc[2][3], w2, xb1);
            fma2(acc[3][0], w3, xa0); fma2(acc[3][1], w3, xa1); fma2(acc[3][2], w3, xb0); fma2(acc[3][3], w3, xb1);
        }
        __syncthreads();
    }
#pragma unroll
    for (int oj = 0; oj < 4; oj++) {
        long long rb = (long long)(to * 4 + oj) * Tt;
        *(u64*)&Op[rb + tt * 4]          = acc[oj][0];
        *(u64*)&Op[rb + tt * 4 + 2]      = acc[oj][1];
        *(u64*)&Op[rb + 64 + tt * 4]     = acc[oj][2];
        *(u64*)&Op[rb + 64 + tt * 4 + 2] = acc[oj][3];
    }
}

// ---------------- dist: big-tile, low-wavefront, pipelined ----------------
// block = 128 t, 256 threads; 32 chunks of 128 k; thread tile 8t x 8k.
// E plain smem, 2-way-broadcast float4 reads + alu-pipe pk2; C lane-consecutive.
// cbT pre-scaled by -2, acc initialized from ||cb_n||^2 -> accumulator IS the score.
static constexpr int ETS = 132;                  // Es row stride (128 t + pad)
static constexpr int CTS = 132;                  // Cs row stride (128 k + pad)
static constexpr int CSTG = 64 * CTS;            // 8448 floats per stage
static constexpr int SMEM_DIST = (64 * ETS + 2 * CSTG + 2 * 128 + 128 + 128) * 4;  // 103424 B

__global__ __launch_bounds__(256) void k_dist(const float* __restrict__ cb,
                                              float* __restrict__ out)
{
    extern __shared__ float sm[];
    float* Es    = sm;                           // [64 o][132]
    float* CsB   = sm + 64 * ETS;                // [2][64 o][132]
    float* cb2   = sm + 64 * ETS + 2 * CSTG;     // [2][128]
    float* den   = cb2 + 256;                    // [128]
    int*   scode = (int*)(den + 128);            // [128]
    float* redv  = CsB;                          // overlap after chunk loop
    int*   redi  = (int*)(CsB + 2048);

    int b = blockIdx.y, tid = threadIdx.x;
    long long t0 = (long long)blockIdx.x * 128;
    int tx = tid & 15;           // k-octet slot (tx*8 .. +7)
    int ty = tid >> 4;           // t-group of 8 (ty*8 .. +7); 2 groups per warp
    const long long xbase = O_XPROJ + (long long)b * (CC * Tt) + t0;

    // load x_proj tile (8B-aligned region): 64 o x 128 t
#pragma unroll
    for (int it = 0; it < 16; it++) {
        int rr = tid + it * 256;                 // 4096 u64: 64 o x 64 t2
        int o = rr >> 6, t2 = rr & 63;
        *(u64*)&Es[o * ETS + t2 * 2] = *(const u64*)&out[xbase + (long long)o * Tt + t2 * 2];
    }
    __syncthreads();
    if (tid < 128) {
        float s = 0.f;
#pragma unroll 8
        for (int o = 0; o < 64; o++) { float v = Es[o * ETS + tid]; s += v * v; }
        den[tid] = fmaxf(__fsqrt_rn(s), 1e-12f);
    }
    __syncthreads();
#pragma unroll
    for (int it = 0; it < 16; it++) {
        int rr = tid + it * 256;
        int o = rr >> 6, t2 = rr & 63;
        float2 v = upk2(*(const u64*)&Es[o * ETS + t2 * 2]);
        v.x = __fdiv_rn(v.x, den[t2 * 2]);
        v.y = __fdiv_rn(v.y, den[t2 * 2 + 1]);
        *(u64*)&Es[o * ETS + t2 * 2] = pk2(v.x, v.y);
    }

    auto loadc = [&](int st, int kc0) {
        float* Cs = CsB + st * CSTG;
#pragma unroll
        for (int it = 0; it < 8; it++) {
            int rr = tid + it * 256;             // 2048 quads: 64 o x 32 k4
            int o = rr >> 5, k4 = rr & 31;
            cp16(s2u(&Cs[o * CTS + k4 * 4]), &g_cbT[o * Kk + kc0 + k4 * 4]);
        }
        if (tid < 32) cp16(s2u(&cb2[st * 128 + tid * 4]), &g_cbn2[kc0 + tid * 4]);
    };

    float bval[8]; int bidx[8];
#pragma unroll
    for (int i = 0; i < 8; i++) { bval[i] = 3.4028235e38f; bidx[i] = 0; }

    loadc(0, 0); cpcommit();
    for (int ch = 0; ch < 32; ch++) {
        if (ch + 1 < 32) loadc((ch + 1) & 1, (ch + 1) * 128);
        cpcommit();
        cpwait1();
        __syncthreads();
        const float* Cs = CsB + (ch & 1) * CSTG;
        const float* cbn2s = cb2 + (ch & 1) * 128;
        int kc0 = ch * 128;

        const u64* ip = (const u64*)&cbn2s[tx * 8];
        u64 i0 = ip[0], i1 = ip[1], i2 = ip[2], i3 = ip[3];
        u64 acc[8][4];
#pragma unroll
        for (int tl = 0; tl < 8; tl++) {
            acc[tl][0] = i0; acc[tl][1] = i1; acc[tl][2] = i2; acc[tl][3] = i3;
        }

#pragma unroll 4
        for (int o = 0; o < 64; o++) {
            const u64* cp = (const u64*)&Cs[o * CTS + tx * 8];
            u64 c0 = cp[0], c1 = cp[1], c2 = cp[2], c3 = cp[3];
            float4 ea = *(const float4*)&Es[o * ETS + ty * 8];       // 2-way bcast
            float4 eb = *(const float4*)&Es[o * ETS + ty * 8 + 4];
            u64 e0 = pk2(ea.x, ea.x), e1 = pk2(ea.y, ea.y), e2 = pk2(ea.z, ea.z), e3 = pk2(ea.w, ea.w);
            u64 e4 = pk2(eb.x, eb.x), e5 = pk2(eb.y, eb.y), e6 = pk2(eb.z, eb.z), e7 = pk2(eb.w, eb.w);
            fma2(acc[0][0], e0, c0); fma2(acc[0][1], e0, c1); fma2(acc[0][2], e0, c2); fma2(acc[0][3], e0, c3);
            fma2(acc[1][0], e1, c0); fma2(acc[1][1], e1, c1); fma2(acc[1][2], e1, c2); fma2(acc[1][3], e1, c3);
            fma2(acc[2][0], e2, c0); fma2(acc[2][1], e2, c1); fma2(acc[2][2], e2, c2); fma2(acc[2][3], e2, c3);
            fma2(acc[3][0], e3, c0); fma2(acc[3][1], e3, c1); fma2(acc[3][2], e3, c2); fma2(acc[3][3], e3, c3);
            fma2(acc[4][0], e4, c0); fma2(acc[4][1], e4, c1); fma2(acc[4][2], e4, c2); fma2(acc[4][3], e4, c3);
            fma2(acc[5][0], e5, c0); fma2(acc[5][1], e5, c1); fma2(acc[5][2], e5, c2); fma2(acc[5][3], e5, c3);
            fma2(acc[6][0], e6, c0); fma2(acc[6][1], e6, c1); fma2(acc[6][2], e6, c2); fma2(acc[6][3], e6, c3);
            fma2(acc[7][0], e7, c0); fma2(acc[7][1], e7, c1); fma2(acc[7][2], e7, c2); fma2(acc[7][3], e7, c3);
        }
        // ascending k within thread; strict < keeps first min (matches jnp.argmin)
#pragma unroll
        for (int tl = 0; tl < 8; tl++) {
#pragma unroll
            for (int j = 0; j < 4; j++) {
                float2 d = upk2(acc[tl][j]);
                int kg = kc0 + tx * 8 + j * 2;
                if (d.x < bval[tl]) { bval[tl] = d.x; bidx[tl] = kg; }
                if (d.y < bval[tl]) { bval[tl] = d.y; bidx[tl] = kg + 1; }
            }
        }
        __syncthreads();
    }
    // cross-thread argmin reduction over the 16 k-slots per t
#pragma unroll
    for (int tl = 0; tl < 8; tl++) {
        redv[(ty * 8 + tl) * 16 + tx] = bval[tl];
        redi[(ty * 8 + tl) * 16 + tx] = bidx[tl];
    }
    __syncthreads();
    if (tid < 128) {
        float bv = 3.4028235e38f; int bi = 0x7fffffff;
#pragma unroll
        for (int j = 0; j < 16; j++) {
            float v = redv[tid * 16 + j]; int i = redi[tid * 16 + j];
            if (v < bv || (v == bv && i < bi)) { bv = v; bi = i; }
        }
        scode[tid] = bi;
        out[O_CODES + (long long)b * Tt + t0 + tid] = (float)bi;
    }
    __syncthreads();

    // gather q, write quantized_proj = xp + (q - xp), accumulate loss
    {
        int t = tid & 127, og = tid >> 7;        // og 0..1 -> 32 o each
        int code = scode[t];
        const float* cbrow = cb + (long long)code * CC + og * 32;
        long long xb2 = O_XPROJ + (long long)b * (CC * Tt) + t0 + t;
        long long qb2 = O_QPROJ + (long long)b * (CC * Tt) + t0 + t;
        float ls = 0.f;
#pragma unroll
        for (int j = 0; j < 32; j++) {
            long long ro = (long long)(og * 32 + j) * Tt;
            float xp = out[xb2 + ro];
            float q  = cbrow[j];
            float d  = q - xp;
            out[qb2 + ro] = xp + d;
            ls += d * d;
        }
        __syncthreads();
        redv[tid] = ls; __syncthreads();
        for (int off = 128; off > 0; off >>= 1) {
            if (tid < off) redv[tid] += redv[tid + off];
            __syncthreads();
        }
        if (tid == 0) g_lpart[blockIdx.y * gridDim.x + blockIdx.x] = (double)redv[0];
    }
}

// ---------------- final loss reduction (256 partials) ----------------
__global__ __launch_bounds__(256) void k_loss(float* __restrict__ out)
{
    __shared__ double sb[256];
    int tid = threadIdx.x;
    sb[tid] = g_lpart[tid];
    __syncthreads();
    for (int off = 128; off > 0; off >>= 1) {
        if (tid < off) sb[tid] += sb[tid + off];
        __syncthreads();
    }
    if (tid == 0) {
        float l = (float)(sb[0] / (double)(16.0 * 64.0 * 2048.0));
        out[O_CBL] = l;
        out[O_CML] = l;
    }
}

extern "C" void kernel_launch(void* const* d_in, const int* in_sizes, int n_in,
                              void* d_out, int out_size) {
    (void)in_sizes; (void)n_in; (void)out_size;
    const float* x    = (const float*)d_in[0];
    const float* v_in = (const float*)d_in[1];
    const float* g_in = (const float*)d_in[2];
    const float* v_out= (const float*)d_in[3];
    const float* g_out= (const float*)d_in[4];
    const float* cb   = (const float*)d_in[5];
    float* out = (float*)d_out;

    cudaFuncSetAttribute(k_dist, cudaFuncAttributeMaxDynamicSharedMemorySize, SMEM_DIST);

    k_prep_win<<<64, 256>>>(v_in, g_in);
    k_prep_wout<<<128, 256>>>(v_out, g_out);
    k_prep_cb<<<512, 256>>>(cb);

    float* winp; cudaGetSymbolAddress((void**)&winp, g_Win);
    float* woutp; cudaGetSymbolAddress((void**)&woutp, g_Wout);

    // x_proj = W_in @ x : per-b 64x2048, K=1024 (R3-proven config)
    k_gemm64<true><<<dim3(16, 16, 1), 256>>>(winp, CE, 0ll,
                                             x, (long long)CE * Tt,
                                             out + O_XPROJ, (long long)CC * Tt, 0ll);

    // codes / qproj / loss partials : 16 t-tiles x 16 b
    k_dist<<<dim3(16, 16), 256, SMEM_DIST>>>(cb, out);
    k_loss<<<1, 256>>>(out);

    // quantized = W_out @ quantized_proj : per-(b, o-block) 64x2048, K=64 (R3-proven)
    k_gemm64<false><<<dim3(16, 16, 16), 256>>>(woutp, CC, (long long)64 * CC,
                                               out + O_QPROJ, (long long)CC * Tt,
                                               out + O_QUANT, (long long)CE * Tt, (long long)64 * Tt);
}